// round 5
// baseline (speedup 1.0000x reference)
#include <cuda_runtime.h>

// ThoughtEngine: B=8, L=1024, D=1024, H=16, HD=64, S=32, C=8. fp32.
// Key invariant: KV of `hidden` is loop-invariant; the step-i query token
// equals buf[:,i-1], so one small QKV projection per step yields both the
// query and the thought-KV slot i-1.

#define LL (size_t)

static const size_t OFF_QKVH = 0;                              // 8192*3072
static const size_t OFF_BUF  = OFF_QKVH + LL 8192 * 3072;      // 8*32*1024
static const size_t OFF_KVB  = OFF_BUF  + LL 8 * 32 * 1024;    // 8*32*2048
static const size_t OFF_CTX  = OFF_KVB  + LL 8 * 32 * 2048;    // 8192
static const size_t OFF_TOK  = OFF_CTX + 8192;
static const size_t OFF_TMP  = OFF_TOK + 8192;
static const size_t OFF_H1   = OFF_TMP + 8192;                 // 8*2048
static const size_t OFF_Q    = OFF_H1 + 16384;
static const size_t OFF_AO   = OFF_Q + 8192;
static const size_t OFF_KVS  = OFF_AO + 8192;                  // 64*2048
static const size_t OFF_SSUM = OFF_KVS + 131072;               // 64*1024
static const size_t OFF_O    = OFF_SSUM + 65536;               // 8192*1024
static const size_t OFF_ATT  = OFF_O + LL 8192 * 1024;         // 8192*1024
static const size_t SCR_TOT  = OFF_ATT + LL 8192 * 1024;

__device__ __align__(16) float g_scratch[SCR_TOT];

__device__ __forceinline__ float geluf(float x) {
    return 0.5f * x * (1.0f + erff(x * 0.7071067811865475f));
}

// ctx[b,d] = mean_l hidden[b,l,d]
__global__ void mean_kernel(const float* __restrict__ hidden, float* __restrict__ ctx) {
    int b = blockIdx.y;
    int d = blockIdx.x * 256 + threadIdx.x;
    const float* p = hidden + LL b * 1048576 + d;
    float s = 0.f;
    #pragma unroll 8
    for (int l = 0; l < 1024; ++l) s += p[LL l * 1024];
    ctx[b * 1024 + d] = s * (1.0f / 1024.0f);
}

__global__ void copy_to_buf(const float* __restrict__ tok, float* __restrict__ buf, int slot) {
    int b = blockIdx.x;
    int d = blockIdx.y * 256 + threadIdx.x;
    buf[LL(b * 32 + slot) * 1024 + d] = tok[b * 1024 + d];
}

// C[M,N] = A[M,K] @ B[N,K]^T + bias.  BM=128 BN=64 BK=16, 256 thr, 8x4 micro.
__global__ __launch_bounds__(256) void sgemm(
    const float* __restrict__ A, const float* __restrict__ B,
    const float* __restrict__ bias, float* __restrict__ C,
    int M, int N, int K)
{
    __shared__ __align__(16) float As[16][128];
    __shared__ __align__(16) float Bs[16][64];
    int tid = threadIdx.x;
    int tx = tid & 15, ty = tid >> 4;
    int bm = blockIdx.y * 128, bn = blockIdx.x * 64;
    float acc[8][4];
    #pragma unroll
    for (int i = 0; i < 8; ++i)
        #pragma unroll
        for (int j = 0; j < 4; ++j) acc[i][j] = 0.f;

    for (int kk = 0; kk < K; kk += 16) {
        #pragma unroll
        for (int s = tid; s < 512; s += 256) {   // A: 128 rows x 4 float4
            int r = s >> 2, c = (s & 3) << 2;
            int gr = bm + r;
            float4 v = make_float4(0.f, 0.f, 0.f, 0.f);
            if (gr < M) v = *reinterpret_cast<const float4*>(A + LL gr * K + kk + c);
            As[c][r] = v.x; As[c + 1][r] = v.y; As[c + 2][r] = v.z; As[c + 3][r] = v.w;
        }
        {
            int r = tid >> 2, c = (tid & 3) << 2; // B: 64 rows x 4 float4
            float4 v = *reinterpret_cast<const float4*>(B + LL(bn + r) * K + kk + c);
            Bs[c][r] = v.x; Bs[c + 1][r] = v.y; Bs[c + 2][r] = v.z; Bs[c + 3][r] = v.w;
        }
        __syncthreads();
        #pragma unroll
        for (int k = 0; k < 16; ++k) {
            float a[8], bb[4];
            #pragma unroll
            for (int i = 0; i < 8; ++i) a[i] = As[k][ty * 8 + i];
            #pragma unroll
            for (int j = 0; j < 4; ++j) bb[j] = Bs[k][tx * 4 + j];
            #pragma unroll
            for (int i = 0; i < 8; ++i)
                #pragma unroll
                for (int j = 0; j < 4; ++j) acc[i][j] += a[i] * bb[j];
        }
        __syncthreads();
    }
    #pragma unroll
    for (int i = 0; i < 8; ++i) {
        int row = bm + ty * 8 + i;
        if (row < M) {
            float* cr = C + LL row * N + bn + tx * 4;
            #pragma unroll
            for (int j = 0; j < 4; ++j) cr[j] = acc[i][j] + bias[bn + tx * 4 + j];
        }
    }
}

// out[b,n] = A[b,:K].W[n,:K] + bias[n], 8 batch rows, one warp per n.
// mode 0 plain, 1 gelu, 2 +residual.
__global__ __launch_bounds__(256) void smallgemm8(
    const float* __restrict__ A, int K,
    const float* __restrict__ W, const float* __restrict__ bias,
    float* __restrict__ out, int N,
    const float* __restrict__ residual, int mode)
{
    __shared__ __align__(16) float As[8 * 1024];
    int tid = threadIdx.x, lane = tid & 31, w = tid >> 5;
    int n = blockIdx.x * 8 + w;
    float acc[8];
    #pragma unroll
    for (int b = 0; b < 8; ++b) acc[b] = 0.f;
    for (int kk = 0; kk < K; kk += 1024) {
        for (int i = tid; i < 8192; i += 256) {
            int b = i >> 10, k = i & 1023;
            As[i] = A[LL b * K + kk + k];
        }
        __syncthreads();
        const float4* wr = reinterpret_cast<const float4*>(W + LL n * K + kk);
        for (int k4 = lane; k4 < 256; k4 += 32) {
            float4 wv = wr[k4];
            #pragma unroll
            for (int b = 0; b < 8; ++b) {
                float4 av = reinterpret_cast<const float4*>(As + b * 1024)[k4];
                acc[b] += wv.x * av.x + wv.y * av.y + wv.z * av.z + wv.w * av.w;
            }
        }
        __syncthreads();
    }
    #pragma unroll
    for (int off = 16; off; off >>= 1)
        #pragma unroll
        for (int b = 0; b < 8; ++b) acc[b] += __shfl_down_sync(0xffffffffu, acc[b], off);
    if (lane == 0) {
        float bv = bias[n];
        #pragma unroll
        for (int b = 0; b < 8; ++b) {
            float v = acc[b] + bv;
            if (mode == 1) v = geluf(v);
            else if (mode == 2) v += residual[b * N + n];
            out[b * N + n] = v;
        }
    }
}

// QKV of tok (8x1024): n<1024 -> q; n in [1024,3072) -> kvbuf slot step-1.
__global__ __launch_bounds__(256) void qkv8(
    const float* __restrict__ tok, const float* __restrict__ W,
    const float* __restrict__ bias, float* __restrict__ q,
    float* __restrict__ kvbuf, int step)
{
    __shared__ __align__(16) float As[8192];
    int tid = threadIdx.x, lane = tid & 31, w = tid >> 5;
    for (int i = tid; i < 8192; i += 256) As[i] = tok[i];
    __syncthreads();
    int n = blockIdx.x * 8 + w;
    const float4* wr = reinterpret_cast<const float4*>(W + LL n * 1024);
    float acc[8];
    #pragma unroll
    for (int b = 0; b < 8; ++b) acc[b] = 0.f;
    for (int k4 = lane; k4 < 256; k4 += 32) {
        float4 wv = wr[k4];
        #pragma unroll
        for (int b = 0; b < 8; ++b) {
            float4 av = reinterpret_cast<const float4*>(As + b * 1024)[k4];
            acc[b] += wv.x * av.x + wv.y * av.y + wv.z * av.z + wv.w * av.w;
        }
    }
    #pragma unroll
    for (int off = 16; off; off >>= 1)
        #pragma unroll
        for (int b = 0; b < 8; ++b) acc[b] += __shfl_down_sync(0xffffffffu, acc[b], off);
    if (lane == 0) {
        float bv = bias[n];
        #pragma unroll
        for (int b = 0; b < 8; ++b) {
            float v = acc[b] + bv;
            if (n < 1024) q[b * 1024 + n] = v;
            else kvbuf[LL(b * 32 + step - 1) * 2048 + (n - 1024)] = v;
        }
    }
}

// Per-step attention: block = (b,h), Lk = 1024 + step keys.
__global__ __launch_bounds__(256) void attn_step(
    const float* __restrict__ q, const float* __restrict__ qkvh,
    const float* __restrict__ kvbuf, float* __restrict__ ao, int Lk)
{
    int b = blockIdx.x >> 4, h = blockIdx.x & 15;
    __shared__ __align__(16) float sq[64];
    __shared__ float sc[1056];
    __shared__ float red[256];
    __shared__ float part[4][64];
    int tid = threadIdx.x;
    if (tid < 64) sq[tid] = q[b * 1024 + h * 64 + tid];
    __syncthreads();

    float lmax = -1e30f;
    for (int j = tid; j < Lk; j += 256) {
        const float* kr = (j < 1024)
            ? qkvh + LL(b * 1024 + j) * 3072 + 1024 + h * 64
            : kvbuf + LL(b * 32 + j - 1024) * 2048 + h * 64;
        const float4* k4 = reinterpret_cast<const float4*>(kr);
        const float4* q4 = reinterpret_cast<const float4*>(sq);
        float s = 0.f;
        #pragma unroll
        for (int d = 0; d < 16; ++d) {
            float4 kv = k4[d], qv = q4[d];
            s += kv.x * qv.x + kv.y * qv.y + kv.z * qv.z + kv.w * qv.w;
        }
        s *= 0.125f;
        sc[j] = s;
        lmax = fmaxf(lmax, s);
    }
    red[tid] = lmax; __syncthreads();
    for (int o = 128; o; o >>= 1) { if (tid < o) red[tid] = fmaxf(red[tid], red[tid + o]); __syncthreads(); }
    float m = red[0];
    __syncthreads();

    float lsum = 0.f;
    for (int j = tid; j < Lk; j += 256) { float p = __expf(sc[j] - m); sc[j] = p; lsum += p; }
    red[tid] = lsum; __syncthreads();
    for (int o = 128; o; o >>= 1) { if (tid < o) red[tid] += red[tid + o]; __syncthreads(); }
    float inv = 1.0f / red[0];

    int d = tid & 63, g = tid >> 6;
    float acc = 0.f;
    for (int j = g; j < Lk; j += 4) {
        const float* vr = (j < 1024)
            ? qkvh + LL(b * 1024 + j) * 3072 + 2048 + h * 64
            : kvbuf + LL(b * 32 + j - 1024) * 2048 + 1024 + h * 64;
        acc += sc[j] * vr[d];
    }
    part[g][d] = acc; __syncthreads();
    if (tid < 64)
        ao[b * 1024 + h * 64 + tid] =
            (part[0][tid] + part[1][tid] + part[2][tid] + part[3][tid]) * inv;
}

// LayerNorm over D=1024 for 8 rows; optionally mirrors into buf slot.
__global__ void ln8(const float* __restrict__ x, const float* __restrict__ gg,
                    const float* __restrict__ bb, float* __restrict__ out,
                    float* __restrict__ buf, int slot)
{
    int b = blockIdx.x, tid = threadIdx.x;
    __shared__ float red[256];
    const float* xr = x + b * 1024;
    float vals[4]; float s = 0.f;
    #pragma unroll
    for (int i = 0; i < 4; ++i) { vals[i] = xr[tid + 256 * i]; s += vals[i]; }
    red[tid] = s; __syncthreads();
    for (int o = 128; o; o >>= 1) { if (tid < o) red[tid] += red[tid + o]; __syncthreads(); }
    float mean = red[0] * (1.0f / 1024.0f);
    __syncthreads();
    float v = 0.f;
    #pragma unroll
    for (int i = 0; i < 4; ++i) { float dd = vals[i] - mean; v += dd * dd; }
    red[tid] = v; __syncthreads();
    for (int o = 128; o; o >>= 1) { if (tid < o) red[tid] += red[tid + o]; __syncthreads(); }
    float inv = rsqrtf(red[0] * (1.0f / 1024.0f) + 1e-5f);
    #pragma unroll
    for (int i = 0; i < 4; ++i) {
        int d = tid + 256 * i;
        float y = (vals[i] - mean) * inv * gg[d] + bb[d];
        out[b * 1024 + d] = y;
        if (buf) buf[LL(b * 32 + slot) * 1024 + d] = y;
    }
}

// cond[l] = LN(hidden[l] + att[l])
__global__ void ln_big(const float* __restrict__ hidden, const float* __restrict__ att,
                       const float* __restrict__ gg, const float* __restrict__ bb,
                       float* __restrict__ out)
{
    int l = blockIdx.x, tid = threadIdx.x;
    __shared__ float red[256];
    const float* hr = hidden + LL l * 1024;
    const float* ar = att + LL l * 1024;
    float vals[4]; float s = 0.f;
    #pragma unroll
    for (int i = 0; i < 4; ++i) { vals[i] = hr[tid + 256 * i] + ar[tid + 256 * i]; s += vals[i]; }
    red[tid] = s; __syncthreads();
    for (int o = 128; o; o >>= 1) { if (tid < o) red[tid] += red[tid + o]; __syncthreads(); }
    float mean = red[0] * (1.0f / 1024.0f);
    __syncthreads();
    float v = 0.f;
    #pragma unroll
    for (int i = 0; i < 4; ++i) { float dd = vals[i] - mean; v += dd * dd; }
    red[tid] = v; __syncthreads();
    for (int o = 128; o; o >>= 1) { if (tid < o) red[tid] += red[tid + o]; __syncthreads(); }
    float inv = rsqrtf(red[0] * (1.0f / 1024.0f) + 1e-5f);
    #pragma unroll
    for (int i = 0; i < 4; ++i) {
        int d = tid + 256 * i;
        out[LL l * 1024 + d] = (vals[i] - mean) * inv * gg[d] + bb[d];
    }
}

// ssum_raw[b,c,:] = softmax_s(comp_q[c].thoughts[b,s] / 32) @ thoughts[b]
__global__ __launch_bounds__(256) void comp_kernel(
    const float* __restrict__ comp_q, const float* __restrict__ thoughts,
    float* __restrict__ ssum)
{
    int b = blockIdx.x >> 3, c = blockIdx.x & 7;
    __shared__ float sc[32];
    __shared__ float pr[32];
    int tid = threadIdx.x, lane = tid & 31, w = tid >> 5;
    const float* qr = comp_q + c * 1024;
    #pragma unroll
    for (int si = 0; si < 4; ++si) {
        int s = w * 4 + si;
        const float* t = thoughts + LL(b * 32 + s) * 1024;
        float acc = 0.f;
        for (int k = lane; k < 1024; k += 32) acc += qr[k] * t[k];
        #pragma unroll
        for (int o = 16; o; o >>= 1) acc += __shfl_down_sync(0xffffffffu, acc, o);
        if (lane == 0) sc[s] = acc * (1.0f / 32.0f);
    }
    __syncthreads();
    if (tid == 0) {
        float m = -1e30f;
        for (int s = 0; s < 32; ++s) m = fmaxf(m, sc[s]);
        float S = 0.f;
        for (int s = 0; s < 32; ++s) { float p = __expf(sc[s] - m); pr[s] = p; S += p; }
        float iv = 1.0f / S;
        for (int s = 0; s < 32; ++s) pr[s] *= iv;
    }
    __syncthreads();
    for (int d = tid; d < 1024; d += 256) {
        float acc = 0.f;
        #pragma unroll
        for (int s = 0; s < 32; ++s) acc += pr[s] * thoughts[LL(b * 32 + s) * 1024 + d];
        ssum[LL(b * 8 + c) * 1024 + d] = acc;
    }
}

// Final MHA: one warp per (row l, head h); 8 keys from kvs (k|v rows).
__global__ __launch_bounds__(256) void final_attn(
    const float* __restrict__ qkvh, const float* __restrict__ kvs,
    float* __restrict__ o)
{
    int tid = threadIdx.x, lane = tid & 31, w = tid >> 5;
    int pair = blockIdx.x * 8 + w;     // 131072 = 8192 rows x 16 heads
    int l = pair >> 4, h = pair & 15;
    int b = l >> 10;
    float2 qv = reinterpret_cast<const float2*>(qkvh + LL l * 3072 + h * 64)[lane];
    float s[8];
    #pragma unroll
    for (int ks = 0; ks < 8; ++ks) {
        float2 kv = reinterpret_cast<const float2*>(kvs + LL(b * 8 + ks) * 2048 + h * 64)[lane];
        float p = qv.x * kv.x + qv.y * kv.y;
        #pragma unroll
        for (int off = 16; off; off >>= 1) p += __shfl_xor_sync(0xffffffffu, p, off);
        s[ks] = p * 0.125f;
    }
    float m = s[0];
    #pragma unroll
    for (int ks = 1; ks < 8; ++ks) m = fmaxf(m, s[ks]);
    float sum = 0.f;
    #pragma unroll
    for (int ks = 0; ks < 8; ++ks) { s[ks] = __expf(s[ks] - m); sum += s[ks]; }
    float inv = 1.0f / sum;
    float o0 = 0.f, o1 = 0.f;
    #pragma unroll
    for (int ks = 0; ks < 8; ++ks) {
        float2 vv = reinterpret_cast<const float2*>(kvs + LL(b * 8 + ks) * 2048 + 1024 + h * 64)[lane];
        o0 += s[ks] * vv.x; o1 += s[ks] * vv.y;
    }
    float2 ov; ov.x = o0 * inv; ov.y = o1 * inv;
    reinterpret_cast<float2*>(o + LL l * 1024 + h * 64)[lane] = ov;
}

extern "C" void kernel_launch(void* const* d_in, const int* in_sizes, int n_in,
                              void* d_out, int out_size) {
    (void)in_sizes; (void)n_in; (void)out_size;
    const float* hidden = (const float*)d_in[0];
    const float* tpw    = (const float*)d_in[1];
    const float* tpb    = (const float*)d_in[2];
    const float* ln1g   = (const float*)d_in[3];
    const float* ln1b   = (const float*)d_in[4];
    const float* ln2g   = (const float*)d_in[5];
    const float* ln2b   = (const float*)d_in[6];
    const float* aiw    = (const float*)d_in[7];
    const float* aib    = (const float*)d_in[8];
    const float* aow    = (const float*)d_in[9];
    const float* aob    = (const float*)d_in[10];
    const float* fw1    = (const float*)d_in[11];
    const float* fb1    = (const float*)d_in[12];
    const float* fw2    = (const float*)d_in[13];
    const float* fb2    = (const float*)d_in[14];
    const float* cq     = (const float*)d_in[15];
    const float* cw     = (const float*)d_in[16];
    const float* cb     = (const float*)d_in[17];
    float* out = (float*)d_out;

    float* S;
    cudaGetSymbolAddress((void**)&S, g_scratch);
    float* QKVH = S + OFF_QKVH;
    float* BUF  = S + OFF_BUF;
    float* KVB  = S + OFF_KVB;
    float* CTX  = S + OFF_CTX;
    float* TOK  = S + OFF_TOK;
    float* TMP  = S + OFF_TMP;
    float* H1   = S + OFF_H1;
    float* Q    = S + OFF_Q;
    float* AO   = S + OFF_AO;
    float* KVS  = S + OFF_KVS;
    float* SSUM = S + OFF_SSUM;
    float* O    = S + OFF_O;
    float* ATT  = S + OFF_ATT;
    float* SUMM = out + LL 8192 * 1024;   // (8,8,1024) tail of output

    // Phase A
    mean_kernel<<<dim3(4, 8), 256>>>(hidden, CTX);
    smallgemm8<<<128, 256>>>(CTX, 1024, tpw, tpb, TOK, 1024, (const float*)0, 0);
    copy_to_buf<<<dim3(8, 4), 256>>>(TOK, BUF, 0);
    sgemm<<<dim3(48, 64), 256>>>(hidden, aiw, aib, QKVH, 8192, 3072, 1024);

    // Phase B: 31 sequential steps
    for (int i = 1; i < 32; ++i) {
        qkv8<<<384, 256>>>(TOK, aiw, aib, Q, KVB, i);
        attn_step<<<128, 256>>>(Q, QKVH, KVB, AO, 1024 + i);
        smallgemm8<<<128, 256>>>(AO, 1024, aow, aob, TMP, 1024, TOK, 2);
        ln8<<<8, 256>>>(TMP, ln1g, ln1b, TOK, (float*)0, 0);
        smallgemm8<<<256, 256>>>(TOK, 1024, fw1, fb1, H1, 2048, (const float*)0, 1);
        smallgemm8<<<128, 256>>>(H1, 2048, fw2, fb2, TMP, 1024, TOK, 2);
        ln8<<<8, 256>>>(TMP, ln2g, ln2b, TOK, BUF, i);
    }

    // Phase C
    comp_kernel<<<64, 256>>>(cq, BUF, SSUM);
    sgemm<<<dim3(16, 1), 256>>>(SSUM, cw, cb, SUMM, 64, 1024, 1024);
    sgemm<<<dim3(32, 1), 256>>>(SUMM, aiw + LL 1024 * 1024, aib + 1024, KVS, 64, 2048, 1024);
    final_attn<<<16384, 256>>>(QKVH, KVS, O);
    sgemm<<<dim3(16, 64), 256>>>(O, aow, aob, ATT, 8192, 1024, 1024);
    ln_big<<<8192, 256>>>(hidden, ATT, ln1g, ln1b, out);
}